// round 2
// baseline (speedup 1.0000x reference)
#include <cuda_runtime.h>
#include <math.h>

// Problem constants (fixed shapes from setup_inputs)
#define D 64
#define R 64
#define T 4096
#define B 8
#define NTOK (B * T)                  // 32768
#define STRENGTH 0.1f
#define SC 0.17677669529663687f       // sqrt(2/64)

#define K1_BLOCKS 512                 // 8 batches * 64 chunks
#define CHUNKS_PER_BATCH 64

// Scratch (device globals — no allocation)
__device__ float g_phi[(size_t)NTOK * R];        // 8 MB
__device__ float g_partial[K1_BLOCKS * R];
__device__ float g_grav[NTOK];                   // includes STRENGTH factor

// ---------------------------------------------------------------------------
// K1: per-token mass + phi; phi -> scratch; block partial of sum(mass*phi)
// One warp handles 8 tokens, 4 at a time. 512 blocks cover all SMs.
// ---------------------------------------------------------------------------
__global__ __launch_bounds__(256) void k1_phi_mass(
    const float* __restrict__ coords, const float* __restrict__ w1,
    const float* __restrict__ b1, const float* __restrict__ w2,
    const float* __restrict__ b2, const float* __restrict__ W,
    const float* __restrict__ bR)
{
    __shared__ float s_w1[64 * 68];   // row-major [r][k], stride 68 (conflict-free f4)
    __shared__ float s_Wt[64 * 68];   // W transposed: [r][k]
    __shared__ float s_b1[64], s_w2[64], s_bR[64];
    __shared__ float s_red[8 * 64];

    const int tid = threadIdx.x;

    for (int idx = tid; idx < 4096; idx += 256) {
        int r = idx >> 6, k = idx & 63;
        s_w1[r * 68 + k] = w1[idx];              // w1 is [r][k] row-major
    }
    for (int idx = tid; idx < 4096; idx += 256) {
        int k = idx >> 6, r = idx & 63;
        s_Wt[r * 68 + k] = W[idx];               // W is [k][r] row-major
    }
    if (tid < 64) { s_b1[tid] = b1[tid]; s_w2[tid] = w2[tid]; s_bR[tid] = bR[tid]; }
    __syncthreads();

    const int lane = tid & 31, warp = tid >> 5;
    const int bb = blockIdx.x >> 6, chunk = blockIdx.x & 63;
    const int tokBase = bb * T + chunk * 64 + warp * 8;
    const float b2v = b2[0];

    const float4* w1a = (const float4*)(s_w1 + lane * 68);
    const float4* w1b = (const float4*)(s_w1 + (lane + 32) * 68);
    const float4* Wta = (const float4*)(s_Wt + lane * 68);
    const float4* Wtb = (const float4*)(s_Wt + (lane + 32) * 68);

    float accA = 0.f, accB = 0.f;

    #pragma unroll
    for (int g = 0; g < 2; ++g) {
        const int t0 = tokBase + g * 4;
        const float4* c4 = (const float4*)(coords + (size_t)t0 * D);
        float h0[4] = {0.f,0.f,0.f,0.f}, h1[4] = {0.f,0.f,0.f,0.f};
        float p0[4] = {0.f,0.f,0.f,0.f}, p1[4] = {0.f,0.f,0.f,0.f};

        #pragma unroll
        for (int k4 = 0; k4 < 16; ++k4) {
            float4 wa = w1a[k4], wb = w1b[k4], va = Wta[k4], vb = Wtb[k4];
            #pragma unroll
            for (int j = 0; j < 4; ++j) {
                float4 c = __ldg(&c4[j * 16 + k4]); // token t0+j (uniform broadcast)
                h0[j] = fmaf(c.x, wa.x, h0[j]); h0[j] = fmaf(c.y, wa.y, h0[j]);
                h0[j] = fmaf(c.z, wa.z, h0[j]); h0[j] = fmaf(c.w, wa.w, h0[j]);
                h1[j] = fmaf(c.x, wb.x, h1[j]); h1[j] = fmaf(c.y, wb.y, h1[j]);
                h1[j] = fmaf(c.z, wb.z, h1[j]); h1[j] = fmaf(c.w, wb.w, h1[j]);
                p0[j] = fmaf(c.x, va.x, p0[j]); p0[j] = fmaf(c.y, va.y, p0[j]);
                p0[j] = fmaf(c.z, va.z, p0[j]); p0[j] = fmaf(c.w, va.w, p0[j]);
                p1[j] = fmaf(c.x, vb.x, p1[j]); p1[j] = fmaf(c.y, vb.y, p1[j]);
                p1[j] = fmaf(c.z, vb.z, p1[j]); p1[j] = fmaf(c.w, vb.w, p1[j]);
            }
        }

        #pragma unroll
        for (int j = 0; j < 4; ++j) {
            float hh0 = fmaxf(h0[j] + s_b1[lane], 0.f);
            float hh1 = fmaxf(h1[j] + s_b1[lane + 32], 0.f);
            float mp = fmaf(hh0, s_w2[lane], hh1 * s_w2[lane + 32]);
            mp += __shfl_xor_sync(0xffffffffu, mp, 16);
            mp += __shfl_xor_sync(0xffffffffu, mp, 8);
            mp += __shfl_xor_sync(0xffffffffu, mp, 4);
            mp += __shfl_xor_sync(0xffffffffu, mp, 2);
            mp += __shfl_xor_sync(0xffffffffu, mp, 1);
            float x = mp + b2v;
            // stable fast softplus: max(x,0) + log(1 + exp(-|x|))
            float mass = fmaxf(x, 0.f) + __logf(1.f + __expf(-fabsf(x)));
            float phi0 = SC * __cosf(p0[j] + s_bR[lane]);
            float phi1 = SC * __cosf(p1[j] + s_bR[lane + 32]);
            g_phi[(size_t)(t0 + j) * R + lane] = phi0;
            g_phi[(size_t)(t0 + j) * R + lane + 32] = phi1;
            accA = fmaf(mass, phi0, accA);
            accB = fmaf(mass, phi1, accB);
        }
    }

    s_red[warp * 64 + lane] = accA;
    s_red[warp * 64 + lane + 32] = accB;
    __syncthreads();
    if (tid < 64) {
        float s = 0.f;
        #pragma unroll
        for (int w = 0; w < 8; ++w) s += s_red[w * 64 + tid];
        g_partial[blockIdx.x * 64 + tid] = s;
    }
}

// ---------------------------------------------------------------------------
// K3: fused phisum reduce + grav[t] = STRENGTH * dot(phi[t], phi_sum[batch])
// Each block redundantly reduces its batch's 64 chunk partials (L2-hit).
// ---------------------------------------------------------------------------
__global__ __launch_bounds__(256) void k3_grav()
{
    __shared__ float s_ps[64];
    const int tid = threadIdx.x, lane = tid & 31, warp = tid >> 5;
    const int bb = blockIdx.x >> 6, chunk = blockIdx.x & 63;

    if (tid < 64) {
        float s = 0.f;
        #pragma unroll
        for (int c = 0; c < CHUNKS_PER_BATCH; ++c)
            s += g_partial[(bb * CHUNKS_PER_BATCH + c) * 64 + tid];
        s_ps[tid] = s;
    }
    __syncthreads();

    const int tokBase = bb * T + chunk * 64 + warp * 8;
    const float ps0 = s_ps[lane];
    const float ps1 = s_ps[lane + 32];

    #pragma unroll
    for (int g = 0; g < 2; ++g) {
        const int t0 = tokBase + g * 4;
        float v[4];
        #pragma unroll
        for (int j = 0; j < 4; ++j) {
            const float* ph = g_phi + (size_t)(t0 + j) * R;
            v[j] = fmaf(ph[lane], ps0, ph[lane + 32] * ps1);
        }
        #pragma unroll
        for (int s = 16; s >= 1; s >>= 1) {
            #pragma unroll
            for (int j = 0; j < 4; ++j)
                v[j] += __shfl_xor_sync(0xffffffffu, v[j], s);
        }
        if (lane == 0) {
            g_grav[t0 + 0] = STRENGTH * v[0];
            g_grav[t0 + 1] = STRENGTH * v[1];
            g_grav[t0 + 2] = STRENGTH * v[2];
            g_grav[t0 + 3] = STRENGTH * v[3];
        }
    }
}

// ---------------------------------------------------------------------------
// K4: the roofline — 1 GiB stream of G with fused diagonal add.
// One block per 64x64 tile (1024 float4s); 4 independent ldcs/stcs per thread.
// ---------------------------------------------------------------------------
__global__ __launch_bounds__(256) void k4_copy(const float4* __restrict__ G4,
                                               float4* __restrict__ O4)
{
    const unsigned tile = blockIdx.x;
    const size_t base = (size_t)tile * 1024;
    const float gv = g_grav[tile];               // uniform per block

    float4 v[4];
    #pragma unroll
    for (int k = 0; k < 4; ++k)
        v[k] = __ldcs(G4 + base + k * 256u + threadIdx.x);

    #pragma unroll
    for (int k = 0; k < 4; ++k) {
        const unsigned within = k * 256u + threadIdx.x;
        const int i  = (int)(within >> 4);         // row (16 float4 per row)
        const int j0 = (int)((within & 15u) << 2); // first col of this float4
        const int d  = i - j0;
        if ((unsigned)d < 4u) {
            if      (d == 0) v[k].x += gv;
            else if (d == 1) v[k].y += gv;
            else if (d == 2) v[k].z += gv;
            else             v[k].w += gv;
        }
        __stcs(O4 + base + within, v[k]);
    }
}

// ---------------------------------------------------------------------------
extern "C" void kernel_launch(void* const* d_in, const int* in_sizes, int n_in,
                              void* d_out, int out_size)
{
    const float* G      = (const float*)d_in[0];
    const float* coords = (const float*)d_in[1];
    const float* w1     = (const float*)d_in[2];
    const float* b1     = (const float*)d_in[3];
    const float* w2     = (const float*)d_in[4];
    const float* b2     = (const float*)d_in[5];
    const float* W      = (const float*)d_in[6];
    const float* bR     = (const float*)d_in[7];
    float* out = (float*)d_out;

    k1_phi_mass<<<K1_BLOCKS, 256>>>(coords, w1, b1, w2, b2, W, bR);
    k3_grav<<<K1_BLOCKS, 256>>>();
    k4_copy<<<NTOK, 256>>>((const float4*)G, (float4*)out);
}

// round 4
// speedup vs baseline: 1.2080x; 1.2080x over previous
#include <cuda_runtime.h>
#include <math.h>

// Problem constants (fixed shapes from setup_inputs)
#define D 64
#define R 64
#define T 4096
#define B 8
#define NTOK (B * T)                  // 32768
#define STRENGTH 0.1f
#define SC 0.17677669529663687f       // sqrt(2/64)

#define K1_BLOCKS 512                 // 8 batches * 64 token-chunks of 64
#define CHUNKS_PER_BATCH 64
#define STRIDE 68                     // smem row stride (floats): 16B-aligned rows

// dynamic smem layout (floats)
#define OFF_W 0                       // [128][68]  combined weights (GEMM) / s_phi alias (epilogue)
#define OFF_C (128 * STRIDE)          // [64][68]   coords (GEMM) / s_h alias (epilogue)
#define OFF_B1 (OFF_C + 64 * STRIDE)  // [64]
#define OFF_W2 (OFF_B1 + 64)          // [64]
#define OFF_BR (OFF_W2 + 64)          // [64]
#define OFF_RED (OFF_BR + 64)         // [512]
#define SMEM_FLOATS (OFF_RED + 512)
#define SMEM_BYTES (SMEM_FLOATS * 4)  // 55040 B

// Scratch (device globals — no allocation)
__device__ float g_phi[(size_t)NTOK * R];        // 8 MB
__device__ float g_partial[K1_BLOCKS * R];
__device__ float g_grav[NTOK];                   // includes STRENGTH factor

// ---------------------------------------------------------------------------
// K1: tiled GEMM coords @ [w1^T | W] with fused relu/softplus/cos epilogue.
// Block: 256 threads, 64 tokens. Thread tile: 4 tokens x 8 rows (interleaved).
// ---------------------------------------------------------------------------
__global__ __launch_bounds__(256) void k1_phi_mass(
    const float* __restrict__ coords, const float* __restrict__ w1,
    const float* __restrict__ b1, const float* __restrict__ w2,
    const float* __restrict__ b2, const float* __restrict__ W,
    const float* __restrict__ bR)
{
    extern __shared__ float sm[];
    float* s_w   = sm + OFF_W;     // combined weight rows: 0-63 = w1, 64-127 = W^T
    float* s_c   = sm + OFF_C;
    float* s_h   = sm + OFF_C;     // alias (coords dead after GEMM)
    float* s_phi = sm + OFF_W;     // alias (weights dead after GEMM)
    float* s_b1  = sm + OFF_B1;
    float* s_w2  = sm + OFF_W2;
    float* s_bR  = sm + OFF_BR;
    float* s_red = sm + OFF_RED;

    const int tid = threadIdx.x;
    const int bb = blockIdx.x >> 6, chunk = blockIdx.x & 63;
    const int tokBase = bb * T + chunk * 64;

    // --- stage weights + coords ---
    for (int idx = tid; idx < 4096; idx += 256) {
        int r = idx >> 6, k = idx & 63;
        s_w[r * STRIDE + k] = w1[idx];                 // w1[r][k]
    }
    for (int idx = tid; idx < 4096; idx += 256) {
        int k = idx >> 6, r = idx & 63;
        s_w[(64 + r) * STRIDE + k] = W[idx];           // W[k][r] -> row 64+r
    }
    for (int idx = tid; idx < 4096; idx += 256) {
        int t = idx >> 6, k = idx & 63;
        s_c[t * STRIDE + k] = coords[(size_t)(tokBase + t) * D + k];
    }
    if (tid < 64) { s_b1[tid] = b1[tid]; s_w2[tid] = w2[tid]; s_bR[tid] = bR[tid]; }
    __syncthreads();

    // --- GEMM: 4 tokens (tg) x 8 rows (rg + 16*i) ---
    const int tg = tid >> 4;       // 0..15 : tokens tg*4 .. tg*4+3
    const int rg = tid & 15;       // 0..15 : rows rg + 16*i, i=0..7
    float acc[4][8];
    #pragma unroll
    for (int j = 0; j < 4; ++j)
        #pragma unroll
        for (int i = 0; i < 8; ++i) acc[j][i] = 0.f;

    const float* cb = s_c + (tg * 4) * STRIDE;
    const float* wb = s_w + rg * STRIDE;

    #pragma unroll 4
    for (int k4 = 0; k4 < 16; ++k4) {
        float4 c[4], w[8];
        #pragma unroll
        for (int j = 0; j < 4; ++j)
            c[j] = *(const float4*)(cb + j * STRIDE + k4 * 4);
        #pragma unroll
        for (int i = 0; i < 8; ++i)
            w[i] = *(const float4*)(wb + i * 16 * STRIDE + k4 * 4);
        #pragma unroll
        for (int j = 0; j < 4; ++j)
            #pragma unroll
            for (int i = 0; i < 8; ++i) {
                acc[j][i] = fmaf(c[j].x, w[i].x, acc[j][i]);
                acc[j][i] = fmaf(c[j].y, w[i].y, acc[j][i]);
                acc[j][i] = fmaf(c[j].z, w[i].z, acc[j][i]);
                acc[j][i] = fmaf(c[j].w, w[i].w, acc[j][i]);
            }
    }
    __syncthreads();   // weights/coords dead; safe to overwrite aliases

    // --- epilogue: h -> relu -> s_h ; p -> phi -> g_phi + s_phi ---
    #pragma unroll
    for (int j = 0; j < 4; ++j) {
        const int tl = tg * 4 + j;
        const int gtok = tokBase + tl;
        #pragma unroll
        for (int i = 0; i < 4; ++i) {
            const int hrow = rg + i * 16;
            s_h[tl * STRIDE + hrow] = fmaxf(acc[j][i] + s_b1[hrow], 0.f);
        }
        #pragma unroll
        for (int i = 4; i < 8; ++i) {
            const int prow = rg + (i - 4) * 16;
            const float ph = SC * __cosf(acc[j][i] + s_bR[prow]);
            g_phi[(size_t)gtok * R + prow] = ph;
            s_phi[tl * STRIDE + prow] = ph;
        }
    }
    __syncthreads();

    // --- mass + block partial of sum(mass * phi) ---
    const int lane = tid & 31, warp = tid >> 5;
    const float b2v = b2[0];
    float accA = 0.f, accB = 0.f;

    #pragma unroll
    for (int jt = 0; jt < 8; ++jt) {
        const int tl = warp * 8 + jt;
        const float h0 = s_h[tl * STRIDE + lane];
        const float h1 = s_h[tl * STRIDE + lane + 32];
        float mp = fmaf(h0, s_w2[lane], h1 * s_w2[lane + 32]);
        mp += __shfl_xor_sync(0xffffffffu, mp, 16);
        mp += __shfl_xor_sync(0xffffffffu, mp, 8);
        mp += __shfl_xor_sync(0xffffffffu, mp, 4);
        mp += __shfl_xor_sync(0xffffffffu, mp, 2);
        mp += __shfl_xor_sync(0xffffffffu, mp, 1);
        const float x = mp + b2v;
        const float mass = fmaxf(x, 0.f) + __logf(1.f + __expf(-fabsf(x)));
        accA = fmaf(mass, s_phi[tl * STRIDE + lane], accA);
        accB = fmaf(mass, s_phi[tl * STRIDE + lane + 32], accB);
    }

    s_red[warp * 64 + lane] = accA;
    s_red[warp * 64 + lane + 32] = accB;
    __syncthreads();
    if (tid < 64) {
        float s = 0.f;
        #pragma unroll
        for (int w = 0; w < 8; ++w) s += s_red[w * 64 + tid];
        g_partial[blockIdx.x * 64 + tid] = s;
    }
}

// ---------------------------------------------------------------------------
// K3: fused phisum reduce + grav[t] = STRENGTH * dot(phi[t], phi_sum[batch])
// ---------------------------------------------------------------------------
__global__ __launch_bounds__(256) void k3_grav()
{
    __shared__ float s_ps[64];
    const int tid = threadIdx.x, lane = tid & 31, warp = tid >> 5;
    const int bb = blockIdx.x >> 6, chunk = blockIdx.x & 63;

    if (tid < 64) {
        float s = 0.f;
        #pragma unroll
        for (int c = 0; c < CHUNKS_PER_BATCH; ++c)
            s += g_partial[(bb * CHUNKS_PER_BATCH + c) * 64 + tid];
        s_ps[tid] = s;
    }
    __syncthreads();

    const int tokBase = bb * T + chunk * 64 + warp * 8;
    const float ps0 = s_ps[lane];
    const float ps1 = s_ps[lane + 32];

    #pragma unroll
    for (int g = 0; g < 2; ++g) {
        const int t0 = tokBase + g * 4;
        float v[4];
        #pragma unroll
        for (int j = 0; j < 4; ++j) {
            const float* ph = g_phi + (size_t)(t0 + j) * R;
            v[j] = fmaf(ph[lane], ps0, ph[lane + 32] * ps1);
        }
        #pragma unroll
        for (int s = 16; s >= 1; s >>= 1) {
            #pragma unroll
            for (int j = 0; j < 4; ++j)
                v[j] += __shfl_xor_sync(0xffffffffu, v[j], s);
        }
        if (lane == 0) {
            g_grav[t0 + 0] = STRENGTH * v[0];
            g_grav[t0 + 1] = STRENGTH * v[1];
            g_grav[t0 + 2] = STRENGTH * v[2];
            g_grav[t0 + 3] = STRENGTH * v[3];
        }
    }
}

// ---------------------------------------------------------------------------
// K4: the roofline — 1 GiB stream of G with fused diagonal add.
// ---------------------------------------------------------------------------
__global__ __launch_bounds__(256) void k4_copy(const float4* __restrict__ G4,
                                               float4* __restrict__ O4)
{
    const unsigned tile = blockIdx.x;
    const size_t base = (size_t)tile * 1024;
    const float gv = g_grav[tile];               // uniform per block

    float4 v[4];
    #pragma unroll
    for (int k = 0; k < 4; ++k)
        v[k] = __ldcs(G4 + base + k * 256u + threadIdx.x);

    #pragma unroll
    for (int k = 0; k < 4; ++k) {
        const unsigned within = k * 256u + threadIdx.x;
        const int i  = (int)(within >> 4);
        const int j0 = (int)((within & 15u) << 2);
        const int d  = i - j0;
        if ((unsigned)d < 4u) {
            if      (d == 0) v[k].x += gv;
            else if (d == 1) v[k].y += gv;
            else if (d == 2) v[k].z += gv;
            else             v[k].w += gv;
        }
        __stcs(O4 + base + within, v[k]);
    }
}

// ---------------------------------------------------------------------------
extern "C" void kernel_launch(void* const* d_in, const int* in_sizes, int n_in,
                              void* d_out, int out_size)
{
    const float* G      = (const float*)d_in[0];
    const float* coords = (const float*)d_in[1];
    const float* w1     = (const float*)d_in[2];
    const float* b1     = (const float*)d_in[3];
    const float* w2     = (const float*)d_in[4];
    const float* b2     = (const float*)d_in[5];
    const float* W      = (const float*)d_in[6];
    const float* bR     = (const float*)d_in[7];
    float* out = (float*)d_out;

    cudaFuncSetAttribute(k1_phi_mass,
                         cudaFuncAttributeMaxDynamicSharedMemorySize, SMEM_BYTES);

    k1_phi_mass<<<K1_BLOCKS, 256, SMEM_BYTES>>>(coords, w1, b1, w2, b2, W, bR);
    k3_grav<<<K1_BLOCKS, 256>>>();
    k4_copy<<<NTOK, 256>>>((const float4*)G, (float4*)out);
}